// round 3
// baseline (speedup 1.0000x reference)
#include <cuda_runtime.h>

// ExtractLearnableSlices — two-phase: (1) per-head param precompute,
// (2) smem-staged fused channel lerp + time lerp.
//   x: (B=64, C=64, L=16384) f32
//   channel_params/offset_params: (128,) f32
//   out: (B=64, N=128, W=512) f32

#define B_DIM   64
#define C_DIM   64
#define L_DIM   16384
#define N_HEADS 128
#define WIDTH   512

#define THREADS 128
#define SMEM_FLOATS 520   // 130 float4; covers idx in [0, 517] (+1 neighbor)

// Per-head params: {t0, wc, int_as_float(fc*L + l0), int_as_float(cc*L + l0)}
__device__ float4 g_params[N_HEADS];

__global__ __launch_bounds__(N_HEADS) void compute_params_kernel(
    const float* __restrict__ channel_params,
    const float* __restrict__ offset_params)
{
    const int i = threadIdx.x;

    const float cp = channel_params[i];
    const float op = offset_params[i];

    const float sc      = 1.0f / (1.0f + expf(-cp));
    const float desired = sc * (float)(C_DIM - 1);
    const int   fc      = (int)floorf(desired);
    const int   cc      = min(fc + 1, C_DIM - 1);
    const float wc      = desired - (float)fc;

    const float so  = 1.0f / (1.0f + expf(-op));
    const float t0  = so * (float)(L_DIM - WIDTH);
    const int   pf0 = (int)floorf(t0);
    const int   l0  = (pf0 - 1) & ~3;     // float4-aligned origin, >=1 slack below

    g_params[i] = make_float4(t0, wc,
                              __int_as_float(fc * L_DIM + l0),
                              __int_as_float(cc * L_DIM + l0));
}

__global__ __launch_bounds__(THREADS) void extract_slices_kernel(
    const float* __restrict__ x,
    float* __restrict__ out)
{
    __shared__ float v[SMEM_FLOATS];

    const int i   = blockIdx.x;   // head 0..127
    const int b   = blockIdx.y;   // batch 0..63
    const int tid = threadIdx.x;  // 0..127

    const float4 p   = g_params[i];
    const float  t0  = p.x;
    const float  wc  = p.y;
    const int    xfo = __float_as_int(p.z);
    const int    xco = __float_as_int(p.w);
    const int    l0  = xfo & (L_DIM - 1);   // fc*L has low 14 bits zero

    const float* __restrict__ xb = x + (size_t)b * (size_t)(C_DIM * L_DIM);
    const float4* __restrict__ xf4 = (const float4*)(xb + xfo);
    const float4* __restrict__ xc4 = (const float4*)(xb + xco);
    float4* __restrict__ v4 = (float4*)v;

    // ---- stage fused channel lerp: 130 float4 (128 + 2-tail) ----
    {
        const float4 a = xf4[tid];
        const float4 c = xc4[tid];
        float4 r;
        r.x = a.x + wc * (c.x - a.x);
        r.y = a.y + wc * (c.y - a.y);
        r.z = a.z + wc * (c.z - a.z);
        r.w = a.w + wc * (c.w - a.w);
        v4[tid] = r;
    }
    if (tid < 2) {
        const int t = THREADS + tid;
        const float4 a = xf4[t];
        const float4 c = xc4[t];
        float4 r;
        r.x = a.x + wc * (c.x - a.x);
        r.y = a.y + wc * (c.y - a.y);
        r.z = a.z + wc * (c.z - a.z);
        r.w = a.w + wc * (c.w - a.w);
        v4[t] = r;
    }
    __syncthreads();

    // ---- time lerp: 4 outputs/thread, stride-128 (conflict-free LDS, coalesced STG) ----
    float* __restrict__ orow = out + ((size_t)b * N_HEADS + i) * WIDTH + tid;

    #pragma unroll
    for (int k = 0; k < 4; ++k) {
        const float pos = t0 + (float)(tid + k * THREADS);  // exact reference f32 math
        const float pff = floorf(pos);
        const float wt  = pos - pff;
        const int   idx = (int)pff - l0;                    // in [0, 517]
        const float v0  = v[idx];
        const float v1  = v[idx + 1];
        orow[k * THREADS] = v0 + wt * (v1 - v0);
    }
}

extern "C" void kernel_launch(void* const* d_in, const int* in_sizes, int n_in,
                              void* d_out, int out_size)
{
    const float* x  = (const float*)d_in[0];
    const float* ch = (const float*)d_in[1];
    const float* of = (const float*)d_in[2];
    float* out = (float*)d_out;

    compute_params_kernel<<<1, N_HEADS>>>(ch, of);

    dim3 grid(N_HEADS, B_DIM);
    extract_slices_kernel<<<grid, THREADS>>>(x, out);
}

// round 4
// speedup vs baseline: 1.2216x; 1.2216x over previous
#include <cuda_runtime.h>

// ExtractLearnableSlices — single kernel, 2 heads per block, 8 outputs/thread.
//   x: (B=64, C=64, L=16384) f32
//   channel_params/offset_params: (128,) f32
//   out: (B=64, N=128, W=512) f32
//
// Per head: fc/cc/wc, t0 uniform. Stage v[l] = xf[l] + wc*(xc[l]-xf[l]) for a
// 520-float window into smem, then out[j] = lerp(v[pf], v[pf+1], frac) with
// pos = t0 + j computed in f32 exactly as the reference.

#define B_DIM   64
#define C_DIM   64
#define L_DIM   16384
#define N_HEADS 128
#define WIDTH   512

#define THREADS      128
#define HEADS_PER_BLK 2
#define SMEM_FLOATS  520   // 130 float4 per head window

__global__ __launch_bounds__(THREADS) void extract_slices_kernel(
    const float* __restrict__ x,
    const float* __restrict__ channel_params,
    const float* __restrict__ offset_params,
    float* __restrict__ out)
{
    __shared__ float v[HEADS_PER_BLK][SMEM_FLOATS];

    const int i0  = blockIdx.x * HEADS_PER_BLK;  // first head of pair
    const int b   = blockIdx.y;                  // batch
    const int tid = threadIdx.x;                 // 0..127

    const float* __restrict__ xb = x + (size_t)b * (size_t)(C_DIM * L_DIM);

    float t0_h[HEADS_PER_BLK];
    int   l0_h[HEADS_PER_BLK];

    // ---- per-head params + front-issued staging loads (all LDGs before sync) ----
    #pragma unroll
    for (int hh = 0; hh < HEADS_PER_BLK; ++hh) {
        const int i = i0 + hh;
        const float cp = __ldg(&channel_params[i]);
        const float op = __ldg(&offset_params[i]);

        const float sc      = 1.0f / (1.0f + expf(-cp));
        const float desired = sc * (float)(C_DIM - 1);
        const int   fc      = (int)floorf(desired);
        const int   cc      = min(fc + 1, C_DIM - 1);
        const float wc      = desired - (float)fc;

        const float so  = 1.0f / (1.0f + expf(-op));
        const float t0  = so * (float)(L_DIM - WIDTH);
        const int   pf0 = (int)floorf(t0);
        const int   l0  = (pf0 - 1) & ~3;   // float4-aligned, >=1 slack below pf0

        t0_h[hh] = t0;
        l0_h[hh] = l0;

        const float4* __restrict__ xf4 = (const float4*)(xb + fc * L_DIM + l0);
        const float4* __restrict__ xc4 = (const float4*)(xb + cc * L_DIM + l0);
        float4* __restrict__ v4 = (float4*)v[hh];

        // main 128 float4
        {
            const float4 a = xf4[tid];
            const float4 c = xc4[tid];
            float4 r;
            r.x = a.x + wc * (c.x - a.x);
            r.y = a.y + wc * (c.y - a.y);
            r.z = a.z + wc * (c.z - a.z);
            r.w = a.w + wc * (c.w - a.w);
            v4[tid] = r;
        }
        // 2-float4 tail
        if (tid < 2) {
            const int t = THREADS + tid;
            const float4 a = xf4[t];
            const float4 c = xc4[t];
            float4 r;
            r.x = a.x + wc * (c.x - a.x);
            r.y = a.y + wc * (c.y - a.y);
            r.z = a.z + wc * (c.z - a.z);
            r.w = a.w + wc * (c.w - a.w);
            v4[t] = r;
        }
    }
    __syncthreads();

    // ---- time lerp epilogues: 4 outputs/thread per head ----
    #pragma unroll
    for (int hh = 0; hh < HEADS_PER_BLK; ++hh) {
        const float t0 = t0_h[hh];
        const int   l0 = l0_h[hh];
        const float* __restrict__ vh = v[hh];
        float* __restrict__ orow =
            out + ((size_t)b * N_HEADS + (i0 + hh)) * WIDTH + tid;

        #pragma unroll
        for (int k = 0; k < 4; ++k) {
            const float pos = t0 + (float)(tid + k * THREADS);  // exact ref f32 math
            const float pff = floorf(pos);
            const float wt  = pos - pff;
            const int   idx = (int)pff - l0;                    // in [0, 517]
            const float v0  = vh[idx];
            const float v1  = vh[idx + 1];
            orow[k * THREADS] = v0 + wt * (v1 - v0);
        }
    }
}

extern "C" void kernel_launch(void* const* d_in, const int* in_sizes, int n_in,
                              void* d_out, int out_size)
{
    const float* x  = (const float*)d_in[0];
    const float* ch = (const float*)d_in[1];
    const float* of = (const float*)d_in[2];
    float* out = (float*)d_out;

    dim3 grid(N_HEADS / HEADS_PER_BLK, B_DIM);
    extract_slices_kernel<<<grid, THREADS>>>(x, ch, of, out);
}